// round 4
// baseline (speedup 1.0000x reference)
#include <cuda_runtime.h>
#include <cuda_bf16.h>
#include <cstddef>

#define N_MODELS 63

// Each thread handles 4 consecutive samples via int4 loads; rows of `votes`
// are contiguous in samples -> fully coalesced 128B transactions per warp per
// row. c1/c0 accumulated separately, sequentially over m, mirroring the
// reference's two-sum-then-compare fp semantics.
// OUTPUT IS WRITTEN AS float32 0.0/1.0 (round-2 evidence: rel_err was exactly
// 1.0 with int writes => harness interprets d_out as float32).
__global__ void vote4_kernel(const int4* __restrict__ votes,
                             const float* __restrict__ weights,
                             float4* __restrict__ out,
                             int n4) {
    __shared__ float sw[N_MODELS];
    if (threadIdx.x < N_MODELS) sw[threadIdx.x] = weights[threadIdx.x];
    __syncthreads();

    int i = blockIdx.x * blockDim.x + threadIdx.x;
    int stride = gridDim.x * blockDim.x;

    for (; i < n4; i += stride) {
        float c1x = 0.f, c1y = 0.f, c1z = 0.f, c1w = 0.f;
        float c0x = 0.f, c0y = 0.f, c0z = 0.f, c0w = 0.f;
#pragma unroll
        for (int m = 0; m < N_MODELS; m++) {
            int4 v = votes[(size_t)m * (size_t)n4 + (size_t)i];
            float wm = sw[m];
            if (v.x) c1x += wm; else c0x += wm;
            if (v.y) c1y += wm; else c0y += wm;
            if (v.z) c1z += wm; else c0z += wm;
            if (v.w) c1w += wm; else c0w += wm;
        }
        float4 o;
        o.x = (c1x > c0x) ? 1.0f : 0.0f;
        o.y = (c1y > c0y) ? 1.0f : 0.0f;
        o.z = (c1z > c0z) ? 1.0f : 0.0f;
        o.w = (c1w > c0w) ? 1.0f : 0.0f;
        out[i] = o;
    }
}

// Scalar tail (never runs for n = 2e6, kept for generality).
__global__ void vote_tail_kernel(const int* __restrict__ votes,
                                 const float* __restrict__ weights,
                                 float* __restrict__ out,
                                 int n, int start) {
    int i = start + blockIdx.x * blockDim.x + threadIdx.x;
    if (i >= n) return;
    float c1 = 0.f, c0 = 0.f;
    for (int m = 0; m < N_MODELS; m++) {
        float wm = weights[m];
        if (votes[(size_t)m * (size_t)n + (size_t)i]) c1 += wm; else c0 += wm;
    }
    out[i] = (c1 > c0) ? 1.0f : 0.0f;
}

extern "C" void kernel_launch(void* const* d_in, const int* in_sizes, int n_in,
                              void* d_out, int out_size) {
    // Bind inputs by SIZE: the weights vector has exactly N_MODELS elements;
    // the votes matrix is the big one. Derive n from the votes element count
    // rather than trusting out_size units.
    const int* votes = nullptr;
    const float* weights = nullptr;
    long long votes_elems = 0;
    for (int k = 0; k < n_in; k++) {
        if (in_sizes[k] == N_MODELS) {
            weights = (const float*)d_in[k];
        } else {
            votes = (const int*)d_in[k];
            votes_elems = in_sizes[k];
        }
    }
    float* out = (float*)d_out;

    int n = (int)(votes_elems / N_MODELS);   // number of samples (2e6)
    int n4 = n / 4;
    int tail_start = n4 * 4;

    if (n4 > 0) {
        const int threads = 256;
        int blocks = (n4 + threads - 1) / threads;
        vote4_kernel<<<blocks, threads>>>((const int4*)votes, weights,
                                          (float4*)out, n4);
    }
    if (tail_start < n) {
        int rem = n - tail_start;
        vote_tail_kernel<<<(rem + 127) / 128, 128>>>(votes, weights, out, n,
                                                     tail_start);
    }
}